// round 12
// baseline (speedup 1.0000x reference)
#include <cuda_runtime.h>
#include <math.h>

#define NL    2048
#define MODES 4096
#define APL   8

#define F1_BLOCKS 512     // fused stage1+lin1: 8 warps/block -> 4096 lin1 rows
#define X3_BLOCKS 32

// Scratch + sync (allocation-free __device__ globals)
__device__ float g_x3[NL];
__device__ float g_h[MODES];
__device__ int   g_done;   // stage1 completion counter (target 32)
__device__ int   g_fin;    // fused-kernel completion counter (for reset)

__device__ __forceinline__ void l2_prefetch(const void* p) {
    asm volatile("prefetch.global.L2 [%0];" :: "l"(p));
}

// Stable real part of complex tanh(x * (Sr + i*Si)) for real x, fast-fp32.
__device__ __forceinline__ float re_tanh_cmul_f(float x, float Sr, float Si) {
    float a = x * Sr;
    float b = x * Si;
    float aa = fabsf(a);
    float e2 = __expf(-2.0f * aa);     // arg <= 0
    float e4 = e2 * e2;
    float num = 1.0f - e4;
    if (a < 0.0f) num = -num;
    float den = 1.0f + e4 + 2.0f * __cosf(2.0f * b) * e2;
    return __fdividef(num, den);
}

__device__ __forceinline__ float dot4(float4 w, float4 x) {
    return w.x * x.x + w.y * x.y + w.z * x.z + w.w * x.w;
}

// Fused stage1 + lin1. All 512 blocks fit in one wave; waiters depend only
// on blocks 0..31 (scheduled first) -> no deadlock. The spin window is
// covered by the L2 prefetch stream issued up front.
__global__ void __launch_bounds__(256) fused1_kernel(
        const float* __restrict__ model_p,
        const float* __restrict__ w0,
        const float* __restrict__ w1,
        const float* __restrict__ w2,
        const float* __restrict__ lin1_w,
        const float* __restrict__ lin1_b) {
    const int t    = threadIdx.x;   // 0..255
    const int lane = t & 31;
    const int warp = t >> 5;        // 0..7
    const int bid  = blockIdx.x;

    // ---- 1. Prefetch this block's 8 lin1 rows (64KB) into L2 ----
    const float* wblk = lin1_w + (size_t)bid * 8 * NL;
    #pragma unroll
    for (int i = t; i < 512; i += 256)            // 512 x 128B lines
        l2_prefetch(wblk + i * 32);

    // ---- 2. Stage1 on blocks 0..31 (proven R7 body) ----
    if (bid < X3_BLOCKS) {
        __shared__ float Ssh[6];
        __shared__ float red[6][8];

        const int f = bid * 64 + (t & 63);
        float x = __ldg(&model_p[(size_t)f * MODES]);  // column 0 only

        const float4* v0 = reinterpret_cast<const float4*>(w0);
        const float4* v1 = reinterpret_cast<const float4*>(w1);
        const float4* v2 = reinterpret_cast<const float4*>(w2);

        float s0r = 0.f, s0i = 0.f, s1r = 0.f, s1i = 0.f, s2r = 0.f, s2i = 0.f;
        #pragma unroll
        for (int i = t; i < MODES / 2; i += 256) {
            float4 c0 = __ldg(&v0[i]);
            float4 c1 = __ldg(&v1[i]);
            float4 c2 = __ldg(&v2[i]);
            s0r += c0.x + c0.z;  s0i += c0.y + c0.w;
            s1r += c1.x + c1.z;  s1i += c1.y + c1.w;
            s2r += c2.x + c2.z;  s2i += c2.y + c2.w;
        }
        float acc6[6] = {s0r, s0i, s1r, s1i, s2r, s2i};
        #pragma unroll
        for (int k = 0; k < 6; k++) {
            float s = acc6[k];
            #pragma unroll
            for (int o = 16; o > 0; o >>= 1)
                s += __shfl_xor_sync(0xffffffffu, s, o);
            if (lane == 0) red[k][warp] = s;
        }
        __syncthreads();
        if (t < 6) {
            float s = 0.f;
            #pragma unroll
            for (int w = 0; w < 8; w++) s += red[t][w];
            Ssh[t] = s;
        }
        __syncthreads();

        float x3 = re_tanh_cmul_f(x,  Ssh[0], Ssh[1]);
        x3 = re_tanh_cmul_f(x3, Ssh[2], Ssh[3]);
        x3 = re_tanh_cmul_f(x3, Ssh[4], Ssh[5]);
        if (t < 64) g_x3[f] = x3;
        __syncthreads();
        if (t == 0) { __threadfence(); atomicAdd(&g_done, 1); }
    }

    // ---- 3. Wait for x3 (prefetch stream keeps DRAM busy meanwhile) ----
    if (t == 0) {
        volatile int* p = &g_done;
        while (*p < X3_BLOCKS) { __nanosleep(64); }
    }
    __syncthreads();

    // ---- 4. lin1: warp per row, weights mostly L2-resident now ----
    const int r = bid * 8 + warp;
    const float4* __restrict__ row = reinterpret_cast<const float4*>(lin1_w + (size_t)r * NL);

    float a0 = 0.f, a1 = 0.f, a2 = 0.f, a3 = 0.f;
    #pragma unroll
    for (int base = 0; base < NL / 4; base += 128) {   // 4 iters
        int i0 = base + lane;
        float4 wv0 = __ldcs(&row[i0]);
        float4 wv1 = __ldcs(&row[i0 + 32]);
        float4 wv2 = __ldcs(&row[i0 + 64]);
        float4 wv3 = __ldcs(&row[i0 + 96]);
        float4 xv0 = __ldcg(reinterpret_cast<const float4*>(g_x3) + i0);
        float4 xv1 = __ldcg(reinterpret_cast<const float4*>(g_x3) + i0 + 32);
        float4 xv2 = __ldcg(reinterpret_cast<const float4*>(g_x3) + i0 + 64);
        float4 xv3 = __ldcg(reinterpret_cast<const float4*>(g_x3) + i0 + 96);
        a0 += dot4(wv0, xv0);
        a1 += dot4(wv1, xv1);
        a2 += dot4(wv2, xv2);
        a3 += dot4(wv3, xv3);
    }
    float acc = (a0 + a1) + (a2 + a3);
    #pragma unroll
    for (int o = 16; o > 0; o >>= 1)
        acc += __shfl_xor_sync(0xffffffffu, acc, o);
    if (lane == 0)
        g_h[r] = tanhf(acc + lin1_b[r]);

    // ---- 5. Reset sync state for graph replay (last finisher) ----
    __syncthreads();
    if (t == 0) {
        int v = atomicAdd(&g_fin, 1);
        if (v == F1_BLOCKS - 1) {
            g_done = 0;
            g_fin  = 0;
            __threadfence();
        }
    }
}

// lin2 matvec (bit-identical to the measured 53.3us winner): warp per row,
// streaming weight loads, 4 float4 streams per lane.
__global__ void __launch_bounds__(256) lin2_kernel(
        const float* __restrict__ W,
        const float* __restrict__ bias,
        float* __restrict__ out) {
    const int warp = (blockIdx.x * blockDim.x + threadIdx.x) >> 5;
    const int lane = threadIdx.x & 31;

    const float4* __restrict__ row = reinterpret_cast<const float4*>(W + (size_t)warp * MODES);
    const float4* __restrict__ v4  = reinterpret_cast<const float4*>(g_h);

    float acc0 = 0.0f, acc1 = 0.0f, acc2 = 0.0f, acc3 = 0.0f;
    #pragma unroll
    for (int base = 0; base < MODES / 4; base += 128) {   // 8 iters
        int i0 = base + lane;
        float4 w0 = __ldcs(&row[i0]);
        float4 w1 = __ldcs(&row[i0 + 32]);
        float4 w2 = __ldcs(&row[i0 + 64]);
        float4 w3 = __ldcs(&row[i0 + 96]);
        float4 x0 = __ldg(&v4[i0]);
        float4 x1 = __ldg(&v4[i0 + 32]);
        float4 x2 = __ldg(&v4[i0 + 64]);
        float4 x3 = __ldg(&v4[i0 + 96]);
        acc0 += dot4(w0, x0);
        acc1 += dot4(w1, x1);
        acc2 += dot4(w2, x2);
        acc3 += dot4(w3, x3);
    }
    float acc = (acc0 + acc1) + (acc2 + acc3);
    #pragma unroll
    for (int o = 16; o > 0; o >>= 1)
        acc += __shfl_xor_sync(0xffffffffu, acc, o);

    if (lane == 0)
        out[warp] = acc + bias[warp];
}

extern "C" void kernel_launch(void* const* d_in, const int* in_sizes, int n_in,
                              void* d_out, int out_size) {
    // metadata order: model_p, w_fft_0, w_fft_1, w_fft_2, lin1_w, lin1_b, lin2_w, lin2_b
    const float* model_p = (const float*)d_in[0];
    const float* w0      = (const float*)d_in[1];   // complex64 interleaved
    const float* w1      = (const float*)d_in[2];
    const float* w2      = (const float*)d_in[3];
    const float* lin1_w  = (const float*)d_in[4];   // (4096, 2048)
    const float* lin1_b  = (const float*)d_in[5];   // (4096,)
    const float* lin2_w  = (const float*)d_in[6];   // (16384, 4096)
    const float* lin2_b  = (const float*)d_in[7];   // (16384,)
    float* out = (float*)d_out;                     // 16384

    (void)in_sizes; (void)n_in; (void)out_size;

    // Fused S-sums + chain + lin1 (one wave, prefetch-covered wait)
    fused1_kernel<<<F1_BLOCKS, 256>>>(model_p, w0, w1, w2, lin1_w, lin1_b);

    // out = lin2_w @ h + lin2_b: 16384 rows, warp per row
    lin2_kernel<<<(NL * APL * 32) / 256, 256>>>(lin2_w, lin2_b, out);
}

// round 13
// speedup vs baseline: 1.1242x; 1.1242x over previous
#include <cuda_runtime.h>
#include <math.h>

#define NL    2048
#define MODES 4096
#define APL   8

// Prefetch: warm the head of lin2_w into L2 during stage1's DRAM-idle window.
// 148 blocks x 256 threads, fire-and-forget prefetch.global.L2 (no data dep).
#define PF_BLOCKS   148
#define PF_THREADS  (PF_BLOCKS * 256)
#define PF_BYTES    (48u * 1024u * 1024u)
#define PF_LINES    (PF_BYTES / 128u)

// Scratch (allocation-free, __device__ globals per harness rules)
__device__ float g_x3[NL];
__device__ float g_h[MODES];

__device__ __forceinline__ void l2_prefetch(const void* p) {
    asm volatile("prefetch.global.L2 [%0];" :: "l"(p));
}

// Stable real part of complex tanh(x * (Sr + i*Si)) for real x, fast-fp32.
// Re tanh(a+ib) = sign(a)*(1 - e^{-4|a|}) / (1 + e^{-4|a|} + 2 cos(2b) e^{-2|a|})
__device__ __forceinline__ float re_tanh_cmul_f(float x, float Sr, float Si) {
    float a = x * Sr;
    float b = x * Si;
    float aa = fabsf(a);
    float e2 = __expf(-2.0f * aa);     // arg <= 0
    float e4 = e2 * e2;
    float num = 1.0f - e4;
    if (a < 0.0f) num = -num;
    float den = 1.0f + e4 + 2.0f * __cosf(2.0f * b) * e2;
    return __fdividef(num, den);
}

__device__ __forceinline__ float dot4(float4 w, float4 x) {
    return w.x * x.x + w.y * x.y + w.z * x.z + w.w * x.w;
}

// Stage 1 (R7 body, blocks 0..31) + L2 prefetch arm (blocks 32..179).
// Prefetch blocks only ISSUE prefetch instructions (no register dependency,
// no wait) and exit; the traffic drains during stage1's latency-bound phase.
__global__ void __launch_bounds__(256) stage1_kernel(
        const float* __restrict__ model_p,
        const float* __restrict__ w0,
        const float* __restrict__ w1,
        const float* __restrict__ w2,
        const float* __restrict__ lin2_w) {
    const int t   = threadIdx.x;   // 0..255
    const int bid = blockIdx.x;

    if (bid >= 32) {
        const unsigned g = (bid - 32) * 256 + t;
        const char* base = reinterpret_cast<const char*>(lin2_w);
        for (unsigned i = g; i < PF_LINES; i += PF_THREADS)
            l2_prefetch(base + (size_t)i * 128);
        return;
    }

    const int lane = t & 31;
    const int warp = t >> 5;        // 0..7

    __shared__ float Ssh[6];
    __shared__ float red[6][8];

    const int f = bid * 64 + (t & 63);   // 32 blocks * 64 = 2048 = NL
    float x = __ldg(&model_p[(size_t)f * MODES]);  // only column 0 matters

    const float4* v0 = reinterpret_cast<const float4*>(w0);  // 2 complex / float4
    const float4* v1 = reinterpret_cast<const float4*>(w1);
    const float4* v2 = reinterpret_cast<const float4*>(w2);

    float s0r = 0.f, s0i = 0.f, s1r = 0.f, s1i = 0.f, s2r = 0.f, s2i = 0.f;
    #pragma unroll
    for (int i = t; i < MODES / 2; i += 256) {   // 8 iters x 3 loads
        float4 c0 = __ldg(&v0[i]);
        float4 c1 = __ldg(&v1[i]);
        float4 c2 = __ldg(&v2[i]);
        s0r += c0.x + c0.z;  s0i += c0.y + c0.w;
        s1r += c1.x + c1.z;  s1i += c1.y + c1.w;
        s2r += c2.x + c2.z;  s2i += c2.y + c2.w;
    }
    float acc6[6] = {s0r, s0i, s1r, s1i, s2r, s2i};
    #pragma unroll
    for (int k = 0; k < 6; k++) {
        float s = acc6[k];
        #pragma unroll
        for (int o = 16; o > 0; o >>= 1)
            s += __shfl_xor_sync(0xffffffffu, s, o);
        if (lane == 0) red[k][warp] = s;
    }
    __syncthreads();
    if (t < 6) {
        float s = 0.f;
        #pragma unroll
        for (int w = 0; w < 8; w++) s += red[t][w];
        Ssh[t] = s;
    }
    __syncthreads();

    const float S0r = Ssh[0], S0i = Ssh[1];
    const float S1r = Ssh[2], S1i = Ssh[3];
    const float S2r = Ssh[4], S2i = Ssh[5];

    x = re_tanh_cmul_f(x, S0r, S0i);
    x = re_tanh_cmul_f(x, S1r, S1i);
    x = re_tanh_cmul_f(x, S2r, S2i);
    if (t < 64) g_x3[f] = x;   // threads 64..255 computed a duplicate; drop it
}

// Warp-per-row matvec: out[row] = act(dot(W[row,:], v) + bias[row]).
// W row-major [ROWS, COLS]. 4 independent float4 streams per lane.
// Weights are single-use -> streaming loads (__ldcs) keep the hot vector
// and the prefetched lin2 head resident in L2.
template <int COLS, bool TANH, bool SRC_X3>
__global__ void __launch_bounds__(256) matvec_kernel(
        const float* __restrict__ W,
        const float* __restrict__ bias,
        float* __restrict__ out,
        int rows) {
    const int warp = (blockIdx.x * blockDim.x + threadIdx.x) >> 5;
    const int lane = threadIdx.x & 31;
    if (warp >= rows) return;

    const float* v = SRC_X3 ? g_x3 : g_h;
    const float4* __restrict__ row = reinterpret_cast<const float4*>(W + (size_t)warp * COLS);
    const float4* __restrict__ v4  = reinterpret_cast<const float4*>(v);

    constexpr int N4 = COLS / 4;   // 512 (lin1) or 1024 (lin2)
    float acc0 = 0.0f, acc1 = 0.0f, acc2 = 0.0f, acc3 = 0.0f;
    #pragma unroll
    for (int base = 0; base < N4; base += 128) {
        int i0 = base + lane;
        float4 w0 = __ldcs(&row[i0]);
        float4 w1 = __ldcs(&row[i0 + 32]);
        float4 w2 = __ldcs(&row[i0 + 64]);
        float4 w3 = __ldcs(&row[i0 + 96]);
        float4 x0 = __ldg(&v4[i0]);
        float4 x1 = __ldg(&v4[i0 + 32]);
        float4 x2 = __ldg(&v4[i0 + 64]);
        float4 x3 = __ldg(&v4[i0 + 96]);
        acc0 += dot4(w0, x0);
        acc1 += dot4(w1, x1);
        acc2 += dot4(w2, x2);
        acc3 += dot4(w3, x3);
    }
    float acc = (acc0 + acc1) + (acc2 + acc3);
    #pragma unroll
    for (int o = 16; o > 0; o >>= 1)
        acc += __shfl_xor_sync(0xffffffffu, acc, o);

    if (lane == 0) {
        float r = acc + bias[warp];
        if (TANH) r = tanhf(r);
        if (SRC_X3) g_h[warp] = r;   // stage-2 output lives in scratch
        else        out[warp] = r;
    }
}

extern "C" void kernel_launch(void* const* d_in, const int* in_sizes, int n_in,
                              void* d_out, int out_size) {
    // metadata order: model_p, w_fft_0, w_fft_1, w_fft_2, lin1_w, lin1_b, lin2_w, lin2_b
    const float* model_p = (const float*)d_in[0];
    const float* w0      = (const float*)d_in[1];   // complex64 interleaved
    const float* w1      = (const float*)d_in[2];
    const float* w2      = (const float*)d_in[3];
    const float* lin1_w  = (const float*)d_in[4];   // (4096, 2048)
    const float* lin1_b  = (const float*)d_in[5];   // (4096,)
    const float* lin2_w  = (const float*)d_in[6];   // (16384, 4096)
    const float* lin2_b  = (const float*)d_in[7];   // (16384,)
    float* out = (float*)d_out;                     // 16384

    (void)in_sizes; (void)n_in; (void)out_size;

    // Stage1 (32 blocks) + fire-and-forget lin2 L2 prefetch (148 blocks)
    stage1_kernel<<<32 + PF_BLOCKS, 256>>>(model_p, w0, w1, w2, lin2_w);

    // h = tanh(lin1_w @ x3 + lin1_b): 4096 rows x 2048 cols, warp per row
    matvec_kernel<NL, true, true><<<(MODES * 32) / 256, 256>>>(lin1_w, lin1_b, out, MODES);

    // out = lin2_w @ h + lin2_b: 16384 rows x 4096 cols, warp per row
    matvec_kernel<MODES, false, false><<<(NL * APL * 32) / 256, 256>>>(lin2_w, lin2_b, out, NL * APL);
}

// round 14
// speedup vs baseline: 1.1604x; 1.0322x over previous
#include <cuda_runtime.h>
#include <math.h>

#define NL    2048
#define MODES 4096
#define APL   8

// Prefetch arms (fire-and-forget prefetch.global.L2, no data dependency):
//  - lin1_w: all 32 MB (needed first, right after stage1)
//  - lin2_w: 64 MB head
// Total 96 MB < 126 MB L2. __ldcs on consumers keeps these lines resident.
#define PF1_BLOCKS   74
#define PF1_THREADS  (PF1_BLOCKS * 256)
#define PF1_LINES    (32u * 1024u * 1024u / 128u)

#define PF2_BLOCKS   148
#define PF2_THREADS  (PF2_BLOCKS * 256)
#define PF2_LINES    (64u * 1024u * 1024u / 128u)

// Scratch (allocation-free, __device__ globals per harness rules)
__device__ float g_x3[NL];
__device__ float g_h[MODES];

__device__ __forceinline__ void l2_prefetch(const void* p) {
    asm volatile("prefetch.global.L2 [%0];" :: "l"(p));
}

// Stable real part of complex tanh(x * (Sr + i*Si)) for real x, fast-fp32.
// Re tanh(a+ib) = sign(a)*(1 - e^{-4|a|}) / (1 + e^{-4|a|} + 2 cos(2b) e^{-2|a|})
__device__ __forceinline__ float re_tanh_cmul_f(float x, float Sr, float Si) {
    float a = x * Sr;
    float b = x * Si;
    float aa = fabsf(a);
    float e2 = __expf(-2.0f * aa);     // arg <= 0
    float e4 = e2 * e2;
    float num = 1.0f - e4;
    if (a < 0.0f) num = -num;
    float den = 1.0f + e4 + 2.0f * __cosf(2.0f * b) * e2;
    return __fdividef(num, den);
}

__device__ __forceinline__ float dot4(float4 w, float4 x) {
    return w.x * x.x + w.y * x.y + w.z * x.z + w.w * x.w;
}

// Stage 1 (R7 body, blocks 0..31) + prefetch arms:
//   blocks 32..105   -> lin1_w (32 MB)
//   blocks 106..253  -> lin2_w head (64 MB)
__global__ void __launch_bounds__(256) stage1_kernel(
        const float* __restrict__ model_p,
        const float* __restrict__ w0,
        const float* __restrict__ w1,
        const float* __restrict__ w2,
        const float* __restrict__ lin1_w,
        const float* __restrict__ lin2_w) {
    const int t   = threadIdx.x;   // 0..255
    const int bid = blockIdx.x;

    if (bid >= 32) {
        if (bid < 32 + PF1_BLOCKS) {
            const unsigned g = (bid - 32) * 256 + t;
            const char* base = reinterpret_cast<const char*>(lin1_w);
            for (unsigned i = g; i < PF1_LINES; i += PF1_THREADS)
                l2_prefetch(base + (size_t)i * 128);
        } else {
            const unsigned g = (bid - 32 - PF1_BLOCKS) * 256 + t;
            const char* base = reinterpret_cast<const char*>(lin2_w);
            for (unsigned i = g; i < PF2_LINES; i += PF2_THREADS)
                l2_prefetch(base + (size_t)i * 128);
        }
        return;
    }

    const int lane = t & 31;
    const int warp = t >> 5;        // 0..7

    __shared__ float Ssh[6];
    __shared__ float red[6][8];

    const int f = bid * 64 + (t & 63);   // 32 blocks * 64 = 2048 = NL
    float x = __ldg(&model_p[(size_t)f * MODES]);  // only column 0 matters

    const float4* v0 = reinterpret_cast<const float4*>(w0);  // 2 complex / float4
    const float4* v1 = reinterpret_cast<const float4*>(w1);
    const float4* v2 = reinterpret_cast<const float4*>(w2);

    float s0r = 0.f, s0i = 0.f, s1r = 0.f, s1i = 0.f, s2r = 0.f, s2i = 0.f;
    #pragma unroll
    for (int i = t; i < MODES / 2; i += 256) {   // 8 iters x 3 loads
        float4 c0 = __ldg(&v0[i]);
        float4 c1 = __ldg(&v1[i]);
        float4 c2 = __ldg(&v2[i]);
        s0r += c0.x + c0.z;  s0i += c0.y + c0.w;
        s1r += c1.x + c1.z;  s1i += c1.y + c1.w;
        s2r += c2.x + c2.z;  s2i += c2.y + c2.w;
    }
    float acc6[6] = {s0r, s0i, s1r, s1i, s2r, s2i};
    #pragma unroll
    for (int k = 0; k < 6; k++) {
        float s = acc6[k];
        #pragma unroll
        for (int o = 16; o > 0; o >>= 1)
            s += __shfl_xor_sync(0xffffffffu, s, o);
        if (lane == 0) red[k][warp] = s;
    }
    __syncthreads();
    if (t < 6) {
        float s = 0.f;
        #pragma unroll
        for (int w = 0; w < 8; w++) s += red[t][w];
        Ssh[t] = s;
    }
    __syncthreads();

    const float S0r = Ssh[0], S0i = Ssh[1];
    const float S1r = Ssh[2], S1i = Ssh[3];
    const float S2r = Ssh[4], S2i = Ssh[5];

    x = re_tanh_cmul_f(x, S0r, S0i);
    x = re_tanh_cmul_f(x, S1r, S1i);
    x = re_tanh_cmul_f(x, S2r, S2i);
    if (t < 64) g_x3[f] = x;   // threads 64..255 computed a duplicate; drop it
}

// Warp-per-row matvec: out[row] = act(dot(W[row,:], v) + bias[row]).
// W row-major [ROWS, COLS]. 4 independent float4 streams per lane.
// Weights single-use -> __ldcs streaming loads (keeps prefetched lines and
// the hot vector resident).
template <int COLS, bool TANH, bool SRC_X3>
__global__ void __launch_bounds__(256) matvec_kernel(
        const float* __restrict__ W,
        const float* __restrict__ bias,
        float* __restrict__ out,
        int rows) {
    const int warp = (blockIdx.x * blockDim.x + threadIdx.x) >> 5;
    const int lane = threadIdx.x & 31;
    if (warp >= rows) return;

    const float* v = SRC_X3 ? g_x3 : g_h;
    const float4* __restrict__ row = reinterpret_cast<const float4*>(W + (size_t)warp * COLS);
    const float4* __restrict__ v4  = reinterpret_cast<const float4*>(v);

    constexpr int N4 = COLS / 4;   // 512 (lin1) or 1024 (lin2)
    float acc0 = 0.0f, acc1 = 0.0f, acc2 = 0.0f, acc3 = 0.0f;
    #pragma unroll
    for (int base = 0; base < N4; base += 128) {
        int i0 = base + lane;
        float4 w0 = __ldcs(&row[i0]);
        float4 w1 = __ldcs(&row[i0 + 32]);
        float4 w2 = __ldcs(&row[i0 + 64]);
        float4 w3 = __ldcs(&row[i0 + 96]);
        float4 x0 = __ldg(&v4[i0]);
        float4 x1 = __ldg(&v4[i0 + 32]);
        float4 x2 = __ldg(&v4[i0 + 64]);
        float4 x3 = __ldg(&v4[i0 + 96]);
        acc0 += dot4(w0, x0);
        acc1 += dot4(w1, x1);
        acc2 += dot4(w2, x2);
        acc3 += dot4(w3, x3);
    }
    float acc = (acc0 + acc1) + (acc2 + acc3);
    #pragma unroll
    for (int o = 16; o > 0; o >>= 1)
        acc += __shfl_xor_sync(0xffffffffu, acc, o);

    if (lane == 0) {
        float r = acc + bias[warp];
        if (TANH) r = tanhf(r);
        if (SRC_X3) g_h[warp] = r;   // stage-2 output lives in scratch
        else        out[warp] = r;
    }
}

extern "C" void kernel_launch(void* const* d_in, const int* in_sizes, int n_in,
                              void* d_out, int out_size) {
    // metadata order: model_p, w_fft_0, w_fft_1, w_fft_2, lin1_w, lin1_b, lin2_w, lin2_b
    const float* model_p = (const float*)d_in[0];
    const float* w0      = (const float*)d_in[1];   // complex64 interleaved
    const float* w1      = (const float*)d_in[2];
    const float* w2      = (const float*)d_in[3];
    const float* lin1_w  = (const float*)d_in[4];   // (4096, 2048)
    const float* lin1_b  = (const float*)d_in[5];   // (4096,)
    const float* lin2_w  = (const float*)d_in[6];   // (16384, 4096)
    const float* lin2_b  = (const float*)d_in[7];   // (16384,)
    float* out = (float*)d_out;                     // 16384

    (void)in_sizes; (void)n_in; (void)out_size;

    // Stage1 (32 blocks) + prefetch arms: lin1_w full + lin2_w 64MB head
    stage1_kernel<<<32 + PF1_BLOCKS + PF2_BLOCKS, 256>>>(
        model_p, w0, w1, w2, lin1_w, lin2_w);

    // h = tanh(lin1_w @ x3 + lin1_b): 4096 rows x 2048 cols, warp per row
    matvec_kernel<NL, true, true><<<(MODES * 32) / 256, 256>>>(lin1_w, lin1_b, out, MODES);

    // out = lin2_w @ h + lin2_b: 16384 rows x 4096 cols, warp per row
    matvec_kernel<MODES, false, false><<<(NL * APL * 32) / 256, 256>>>(lin2_w, lin2_b, out, NL * APL);
}